// round 7
// baseline (speedup 1.0000x reference)
#include <cuda_runtime.h>

#define BIGZ 1000000.0f
constexpr int N_ = 8, H_ = 512, W_ = 512, C_ = 32, F_ = 20000, V_ = 10002;
constexpr int HW = H_ * W_;  // 262144

constexpr long long OFF_OUTMAP = 0LL;
constexpr long long OFF_VV     = 67108864LL;
constexpr long long OFF_MASK   = 67118866LL;
constexpr long long OFF_ZB     = 69216018LL;
constexpr long long OFF_P      = 71313170LL;
constexpr long long OFF_D      = 73410322LL;
constexpr long long OFF_BC     = 75507474LL;

// zero at module load; the fused tail restores all-zero after each use, so
// every graph replay sees identical initial state.
__device__ int g_face_flag[F_];
__device__ unsigned int g_ticket;  // zero-init; reset by last block each run

__device__ __forceinline__ void stcs4(float* p, float a, float b, float c, float d) {
    float4 v = make_float4(a, b, c, d);
    __stcs((float4*)p, v);
}
__device__ __forceinline__ void stcs2(float* p, float a, float b) {
    float2 v = make_float2(a, b);
    __stcs((float2*)p, v);
}

// ---------------------------------------------------------------------------
// Fully fused kernel. Per-pixel pass identical to the 90.3us R4 version
// (predicated 8-layer gather — the single-gather restructure regressed).
// After all CTAs finish, the LAST CTA (atomic ticket) runs the face->vertex
// visibility scatter and resets flags/counter for the next graph replay.
// ---------------------------------------------------------------------------
__global__ __launch_bounds__(128) void raster_k(
    const float* __restrict__ zbuf,
    const int*   __restrict__ ptf,
    const float* __restrict__ bary,
    const float* __restrict__ dists,
    const float* __restrict__ fm,
    const int*   __restrict__ faces,
    float*       __restrict__ out)
{
    int g = blockIdx.x * blockDim.x + threadIdx.x;  // 0 .. HW/4-1
    if (g < V_) out[OFF_VV + g] = 0.0f;
    int pix = g << 2;

    // ---- pass 1: coverage count + first-argmin over the 8 layers ----------
    float z[8][4];
    float minv[4];
    int   mini[4];
    int   cnt[4];
#pragma unroll
    for (int j = 0; j < 4; j++) { minv[j] = 3.0e38f; mini[j] = 0; cnt[j] = 0; }

#pragma unroll
    for (int n = 0; n < 8; n++) {
        float4 zz = __ldcs((const float4*)(zbuf + n * HW + pix));
        z[n][0] = zz.x; z[n][1] = zz.y; z[n][2] = zz.z; z[n][3] = zz.w;
#pragma unroll
        for (int j = 0; j < 4; j++) {
            float v = z[n][j];
            cnt[j] += (v > -1.0f) ? 1 : 0;
            float tmp = (v < 0.0f) ? BIGZ : v;
            if (tmp < minv[j]) { minv[j] = tmp; mini[j] = n; }
        }
    }

    // ---- pass 2: per layer, emit masked outputs + colors -------------------
#pragma unroll
    for (int n = 0; n < 8; n++) {
        int4   pf4 = __ldcs((const int4*)(ptf + n * HW + pix));
        float4 d4  = __ldcs((const float4*)(dists + n * HW + pix));
        const float* bptr = bary + (long long)(n * HW + pix) * 3;
        float4 bA = __ldcs((const float4*)(bptr));
        float4 bB = __ldcs((const float4*)(bptr + 4));
        float4 bC = __ldcs((const float4*)(bptr + 8));
        float bin[12] = {bA.x, bA.y, bA.z, bA.w, bB.x, bB.y, bB.z, bB.w,
                         bC.x, bC.y, bC.z, bC.w};
        int   pf[4] = {pf4.x, pf4.y, pf4.z, pf4.w};
        float dd[4] = {d4.x, d4.y, d4.z, d4.w};

        float zbo[4], po[4], dto[4], mo[4], bco[12];
        float b0[4], b1[4], b2[4];
        int   pr[4];
        bool  valid[4];
#pragma unroll
        for (int j = 0; j < 4; j++) {
            bool dup = (cnt[j] > 1) && (mini[j] != n);
            int  p   = dup ? -1 : pf[j];
            valid[j] = (p >= 0);
            pr[j]    = valid[j] ? p : 0;
            zbo[j]   = dup ? -1.0f : z[n][j];
            po[j]    = (float)p;
            dto[j]   = dup ? -1.0f : dd[j];
            b0[j]    = dup ? -1.0f : bin[3 * j + 0];
            b1[j]    = dup ? -1.0f : bin[3 * j + 1];
            b2[j]    = dup ? -1.0f : bin[3 * j + 2];
            bco[3 * j + 0] = b0[j];
            bco[3 * j + 1] = b1[j];
            bco[3 * j + 2] = b2[j];
            mo[j] = (z[n][j] >= 0.0f) ? 1.0f : 0.0f;
            if (valid[j]) g_face_flag[pr[j]] = 1;  // idempotent flag store
        }

        // small outputs: regions only 8B-aligned (offsets ≡ 2 mod 4) -> float2
        long long base = (long long)n * HW + pix;
        float* zp = out + OFF_ZB + base;
        stcs2(zp,     zbo[0], zbo[1]); stcs2(zp + 2, zbo[2], zbo[3]);
        float* pp = out + OFF_P + base;
        stcs2(pp,     po[0], po[1]);   stcs2(pp + 2, po[2], po[3]);
        float* dp = out + OFF_D + base;
        stcs2(dp,     dto[0], dto[1]); stcs2(dp + 2, dto[2], dto[3]);
        float* mp = out + OFF_MASK + base;
        stcs2(mp,     mo[0], mo[1]);   stcs2(mp + 2, mo[2], mo[3]);
        float* bp = out + OFF_BC + base * 3;
#pragma unroll
        for (int k = 0; k < 6; k++)
            stcs2(bp + 2 * k, bco[2 * k], bco[2 * k + 1]);

        // colors: out_map[n][c][h][w]; float4 over w, transposed in regs
        float* om = out + OFF_OUTMAP + (long long)n * C_ * HW + pix;
#pragma unroll
        for (int cq = 0; cq < 8; cq++) {
            int c = cq * 4;
            float col[4][4];
#pragma unroll
            for (int j = 0; j < 4; j++) {
                float4 a = make_float4(0.f, 0.f, 0.f, 0.f);
                if (valid[j]) {
                    const float* fb = fm + pr[j] * 96 + c;  // face_memory[p][i][c]
                    float4 f0 = *(const float4*)(fb);
                    float4 f1 = *(const float4*)(fb + 32);
                    float4 f2 = *(const float4*)(fb + 64);
                    a.x = b0[j] * f0.x + b1[j] * f1.x + b2[j] * f2.x;
                    a.y = b0[j] * f0.y + b1[j] * f1.y + b2[j] * f2.y;
                    a.z = b0[j] * f0.z + b1[j] * f1.z + b2[j] * f2.z;
                    a.w = b0[j] * f0.w + b1[j] * f1.w + b2[j] * f2.w;
                }
                col[j][0] = a.x; col[j][1] = a.y; col[j][2] = a.z; col[j][3] = a.w;
            }
#pragma unroll
            for (int k = 0; k < 4; k++)
                stcs4(om + (long long)(c + k) * HW,
                      col[0][k], col[1][k], col[2][k], col[3][k]);
        }
    }

    // ---- fused tail: last CTA performs the vertex-visibility scatter -------
    __threadfence();          // make this CTA's flag/vv stores globally visible
    __syncthreads();
    __shared__ unsigned int s_ticket;
    if (threadIdx.x == 0)
        s_ticket = atomicAdd(&g_ticket, 1u);
    __syncthreads();

    if (s_ticket == gridDim.x - 1) {
        // all other CTAs' stores are visible (they fenced before their add)
        for (int f = threadIdx.x; f < F_; f += 128) {
            int flag = g_face_flag[f];
            int v0 = __ldg(faces + 3 * f + 0);
            int v1 = __ldg(faces + 3 * f + 1);
            int v2 = __ldg(faces + 3 * f + 2);
            if (flag) {
                out[OFF_VV + v0] = 1.0f;
                out[OFF_VV + v1] = 1.0f;
                out[OFF_VV + v2] = 1.0f;
                g_face_flag[f] = 0;   // restore all-zero for next replay
            }
        }
        __syncthreads();
        if (threadIdx.x == 0) g_ticket = 0;  // restore counter for next replay
    }
}

extern "C" void kernel_launch(void* const* d_in, const int* in_sizes, int n_in,
                              void* d_out, int out_size) {
    const float* zbuf  = (const float*)d_in[0];
    const int*   ptf   = (const int*)d_in[1];
    const float* bary  = (const float*)d_in[2];
    const float* dists = (const float*)d_in[3];
    const float* fm    = (const float*)d_in[4];
    const int*   faces = (const int*)d_in[5];
    float* out = (float*)d_out;

    raster_k<<<(HW / 4) / 128, 128>>>(zbuf, ptf, bary, dists, fm, faces, out);
}

// round 9
// speedup vs baseline: 1.7399x; 1.7399x over previous
#include <cuda_runtime.h>

#define BIGZ 1000000.0f
constexpr int N_ = 8, H_ = 512, W_ = 512, C_ = 32, F_ = 20000, V_ = 10002;
constexpr int HW = H_ * W_;  // 262144

constexpr long long OFF_OUTMAP = 0LL;
constexpr long long OFF_VV     = 67108864LL;
constexpr long long OFF_MASK   = 67118866LL;
constexpr long long OFF_ZB     = 69216018LL;
constexpr long long OFF_P      = 71313170LL;
constexpr long long OFF_D      = 73410322LL;
constexpr long long OFF_BC     = 75507474LL;

// zero at module load; vertex_k restores all-zero after each use.
__device__ int g_face_flag[F_];

__device__ __forceinline__ void stcs2(float* p, float a, float b) {
    float2 v = make_float2(a, b);
    __stcs((float2*)p, v);
}

// ---------------------------------------------------------------------------
// Per-pixel pass, 2 pixels/thread (HALVED from 4 to cut register pressure:
// R7 profile showed regs=178 -> occ 12%, latency-bound at DRAM=25%).
// ---------------------------------------------------------------------------
__global__ __launch_bounds__(64) void pixel_k(
    const float* __restrict__ zbuf,
    const int*   __restrict__ ptf,
    const float* __restrict__ bary,
    const float* __restrict__ dists,
    const float* __restrict__ fm,
    float*       __restrict__ out)
{
    int g = blockIdx.x * blockDim.x + threadIdx.x;  // 0 .. HW/2-1
    if (g < V_) out[OFF_VV + g] = 0.0f;
    int pix = g << 1;

    // ---- pass 1: coverage count + first-argmin over the 8 layers ----------
    float z[8][2];
    float minv[2];
    int   mini[2];
    int   cnt[2];
#pragma unroll
    for (int j = 0; j < 2; j++) { minv[j] = 3.0e38f; mini[j] = 0; cnt[j] = 0; }

#pragma unroll
    for (int n = 0; n < 8; n++) {
        float2 zz = __ldcs((const float2*)(zbuf + n * HW + pix));
        z[n][0] = zz.x; z[n][1] = zz.y;
#pragma unroll
        for (int j = 0; j < 2; j++) {
            float v = z[n][j];
            cnt[j] += (v > -1.0f) ? 1 : 0;
            float tmp = (v < 0.0f) ? BIGZ : v;
            if (tmp < minv[j]) { minv[j] = tmp; mini[j] = n; }
        }
    }

    // ---- pass 2: per layer, emit masked outputs + colors -------------------
#pragma unroll
    for (int n = 0; n < 8; n++) {
        int2   pf2 = __ldcs((const int2*)(ptf + n * HW + pix));
        float2 d2  = __ldcs((const float2*)(dists + n * HW + pix));
        const float* bptr = bary + (long long)(n * HW + pix) * 3;
        float2 bA = __ldcs((const float2*)(bptr));
        float2 bB = __ldcs((const float2*)(bptr + 2));
        float2 bC = __ldcs((const float2*)(bptr + 4));
        float bin[6] = {bA.x, bA.y, bB.x, bB.y, bC.x, bC.y};
        int   pf[2] = {pf2.x, pf2.y};
        float dd[2] = {d2.x, d2.y};

        float zbo[2], po[2], dto[2], mo[2], bco[6];
        float b0[2], b1[2], b2[2];
        int   pr[2];
        bool  valid[2];
#pragma unroll
        for (int j = 0; j < 2; j++) {
            bool dup = (cnt[j] > 1) && (mini[j] != n);
            int  p   = dup ? -1 : pf[j];
            valid[j] = (p >= 0);
            pr[j]    = valid[j] ? p : 0;
            zbo[j]   = dup ? -1.0f : z[n][j];
            po[j]    = (float)p;
            dto[j]   = dup ? -1.0f : dd[j];
            b0[j]    = dup ? -1.0f : bin[3 * j + 0];
            b1[j]    = dup ? -1.0f : bin[3 * j + 1];
            b2[j]    = dup ? -1.0f : bin[3 * j + 2];
            bco[3 * j + 0] = b0[j];
            bco[3 * j + 1] = b1[j];
            bco[3 * j + 2] = b2[j];
            mo[j] = (z[n][j] >= 0.0f) ? 1.0f : 0.0f;
            if (valid[j]) g_face_flag[pr[j]] = 1;  // idempotent flag store
        }

        long long base = (long long)n * HW + pix;
        stcs2(out + OFF_ZB + base,   zbo[0], zbo[1]);
        stcs2(out + OFF_P + base,    po[0],  po[1]);
        stcs2(out + OFF_D + base,    dto[0], dto[1]);
        stcs2(out + OFF_MASK + base, mo[0],  mo[1]);
        float* bp = out + OFF_BC + base * 3;
        stcs2(bp,     bco[0], bco[1]);
        stcs2(bp + 2, bco[2], bco[3]);
        stcs2(bp + 4, bco[4], bco[5]);

        // colors: out_map[n][c][h][w]; float2 over w, transposed in regs
        float* om = out + OFF_OUTMAP + (long long)n * C_ * HW + pix;
#pragma unroll
        for (int cq = 0; cq < 8; cq++) {
            int c = cq * 4;
            float col[2][4];
#pragma unroll
            for (int j = 0; j < 2; j++) {
                float4 a = make_float4(0.f, 0.f, 0.f, 0.f);
                if (valid[j]) {
                    const float* fb = fm + pr[j] * 96 + c;  // face_memory[p][i][c]
                    float4 f0 = *(const float4*)(fb);
                    float4 f1 = *(const float4*)(fb + 32);
                    float4 f2 = *(const float4*)(fb + 64);
                    a.x = b0[j] * f0.x + b1[j] * f1.x + b2[j] * f2.x;
                    a.y = b0[j] * f0.y + b1[j] * f1.y + b2[j] * f2.y;
                    a.z = b0[j] * f0.z + b1[j] * f1.z + b2[j] * f2.z;
                    a.w = b0[j] * f0.w + b1[j] * f1.w + b2[j] * f2.w;
                }
                col[j][0] = a.x; col[j][1] = a.y; col[j][2] = a.z; col[j][3] = a.w;
            }
#pragma unroll
            for (int k = 0; k < 4; k++)
                stcs2(om + (long long)(c + k) * HW, col[0][k], col[1][k]);
        }
    }
}

// ---------------------------------------------------------------------------
// Face visibility -> vertex visibility scatter; clears flags for next replay.
// ---------------------------------------------------------------------------
__global__ __launch_bounds__(128) void vertex_k(const int* __restrict__ faces,
                                                float* __restrict__ out) {
    int f = blockIdx.x * blockDim.x + threadIdx.x;
    if (f < F_) {
        int flag = g_face_flag[f];
        int v0 = __ldg(faces + 3 * f + 0);
        int v1 = __ldg(faces + 3 * f + 1);
        int v2 = __ldg(faces + 3 * f + 2);
        if (flag) {
            out[OFF_VV + v0] = 1.0f;
            out[OFF_VV + v1] = 1.0f;
            out[OFF_VV + v2] = 1.0f;
            g_face_flag[f] = 0;
        }
    }
}

extern "C" void kernel_launch(void* const* d_in, const int* in_sizes, int n_in,
                              void* d_out, int out_size) {
    const float* zbuf  = (const float*)d_in[0];
    const int*   ptf   = (const int*)d_in[1];
    const float* bary  = (const float*)d_in[2];
    const float* dists = (const float*)d_in[3];
    const float* fm    = (const float*)d_in[4];
    const int*   faces = (const int*)d_in[5];
    float* out = (float*)d_out;

    pixel_k<<<(HW / 2) / 64, 64>>>(zbuf, ptf, bary, dists, fm, out);
    vertex_k<<<(F_ + 127) / 128, 128>>>(faces, out);
}